// round 8
// baseline (speedup 1.0000x reference)
#include <cuda_runtime.h>
#include <cuda_fp16.h>
#include <math.h>

#define NN 100000
#define DD 128
#define AA 4096
#define SS 512
// 1/TEMP = 10

// Scratch (no device mallocs allowed)
__device__ __half g_xh[(size_t)NN * DD];   // normalized fp16 features, 25.6 MB
__device__ float  g_aloss[AA];
__device__ int    g_done = 0;              // ticket counter for last-block reduce

// ---------------------------------------------------------------------------
// Kernel 1: fused normalize + fp16 convert. FOUR rows per warp:
// all four float4 loads issued back-to-back (MLP=4), four independent
// shuffle-reduce chains interleave in the issue slots. __ldcs: x is read
// exactly once -> evict-first, keep L2 warm for g_xh.
// ---------------------------------------------------------------------------
__global__ void norm_convert_kernel(const float* __restrict__ x) {
    int warp = (blockIdx.x * blockDim.x + threadIdx.x) >> 5;
    int lane = threadIdx.x & 31;
    int r0 = warp * 4;
    if (r0 >= NN) return;

    float4 v[4];
    bool has[4];
#pragma unroll
    for (int k = 0; k < 4; k++) {
        int r = r0 + k;
        has[k] = (r < NN);
        v[k] = has[k]
            ? __ldcs(reinterpret_cast<const float4*>(x + (size_t)r * DD) + lane)
            : make_float4(0.f, 0.f, 0.f, 0.f);
    }

    float s[4];
#pragma unroll
    for (int k = 0; k < 4; k++)
        s[k] = v[k].x * v[k].x + v[k].y * v[k].y + v[k].z * v[k].z + v[k].w * v[k].w;

#pragma unroll
    for (int o = 16; o; o >>= 1) {
#pragma unroll
        for (int k = 0; k < 4; k++)
            s[k] += __shfl_xor_sync(0xFFFFFFFFu, s[k], o);
    }

#pragma unroll
    for (int k = 0; k < 4; k++) {
        if (!has[k]) continue;
        float inv = rsqrtf(s[k]);
        __half2 h[2];
        h[0] = __floats2half2_rn(v[k].x * inv, v[k].y * inv);
        h[1] = __floats2half2_rn(v[k].z * inv, v[k].w * inv);
        reinterpret_cast<uint2*>(g_xh + (size_t)(r0 + k) * DD)[lane] =
            *reinterpret_cast<uint2*>(h);
    }
}

// ---------------------------------------------------------------------------
// Kernel 2: one block (8 warps) per anchor. Half-warp per sample:
// each half-lane owns float4 = 16 B = 8 fp16 -> 16 lanes x 16 B = full 256 B
// row, coalesced. 3-deep software-pipelined prefetch ring hides L2 latency.
// (At ~92% of LTS cap — hot loop untouched.) Final sum fused via last-block
// pattern: the block taking the last ticket does a deterministic fixed-order
// reduction of g_aloss and resets the counter for graph replay.
// ---------------------------------------------------------------------------
__global__ __launch_bounds__(256) void loss_kernel(
    const int* __restrict__ y,
    const int* __restrict__ anchors,
    const int* __restrict__ sampled,
    float* __restrict__ out)
{
    __shared__ int   s_idx[SS];
    __shared__ int   s_y[SS];
    __shared__ float s_num[16], s_den[16], s_cnt[16];
    __shared__ int   s_last;
    __shared__ float s_red[256];

    int a    = blockIdx.x;
    int tid  = threadIdx.x;
    int lane = tid & 31;
    int warp = tid >> 5;     // 0..7
    int hw   = lane >> 4;    // half-warp id (0/1)
    int hl   = lane & 15;    // lane within half-warp

    // Stage sample indices AND labels (random 4B gathers batched here with
    // 256 threads of MLP, out of the hot loop).
    for (int i = tid; i < SS; i += 256) {
        int si = sampled[(size_t)a * SS + i];
        s_idx[i] = si;
        s_y[i]   = y[si];
    }

    int ai = anchors[a];
    int ay = y[ai];

    // Anchor row: 8 fp16 per half-lane (float4 = 16B) -> 8 fp32 registers
    float af[8];
    {
        float4 ar = reinterpret_cast<const float4*>(g_xh + (size_t)ai * DD)[hl];
        const __half2* ah = reinterpret_cast<const __half2*>(&ar);
#pragma unroll
        for (int j = 0; j < 4; j++) {
            float2 f = __half22float2(ah[j]);
            af[2 * j]     = f.x;
            af[2 * j + 1] = f.y;
        }
    }
    __syncthreads();

    const int off = warp * 2 + hw;           // this half-warp's sample slot
    float num = 0.0f, den = 0.0f, cnt = 0.0f;

    // Ring of 3 prefetched sample fragments (each half-lane: 16 B = 8 fp16)
    float4 buf[3];
#pragma unroll
    for (int p = 0; p < 3; p++) {
        int si = s_idx[p * 16 + off];
        buf[p] = reinterpret_cast<const float4*>(g_xh + (size_t)si * DD)[hl];
    }

#pragma unroll
    for (int i = 0; i < 32; i++) {           // 32 samples per half-warp
        float4 cur = buf[i % 3];
        if (i + 3 < 32) {
            int si = s_idx[(i + 3) * 16 + off];
            buf[i % 3] = reinterpret_cast<const float4*>(g_xh + (size_t)si * DD)[hl];
        }
        const __half2* sh = reinterpret_cast<const __half2*>(&cur);
        float d = 0.0f;
#pragma unroll
        for (int j = 0; j < 4; j++) {
            float2 f = __half22float2(sh[j]);
            d = fmaf(af[2 * j],     f.x, d);
            d = fmaf(af[2 * j + 1], f.y, d);
        }
        // 16-lane reduce (xor offsets < 16 stay within the half-warp)
#pragma unroll
        for (int o = 8; o; o >>= 1) d += __shfl_xor_sync(0xFFFFFFFFu, d, o);
        float e = __expf(d * 10.0f);
        den += e;
        if (s_y[i * 16 + off] == ay) { num += e; cnt += 1.0f; }
    }

    if (hl == 0) { s_num[off] = num; s_den[off] = den; s_cnt[off] = cnt; }
    __syncthreads();

    if (tid == 0) {
        float nm = 0.0f, dn = 0.0f, c = 0.0f;
#pragma unroll
        for (int k = 0; k < 16; k++) { nm += s_num[k]; dn += s_den[k]; c += s_cnt[k]; }
        float loss = 0.0f;
        if (c > 0.0f) loss = (logf(dn) - logf(nm)) / c;  // -log(num/den)/cnt
        g_aloss[a] = loss;
        __threadfence();
        int t = atomicAdd(&g_done, 1);
        s_last = (t == AA - 1) ? 1 : 0;
    }
    __syncthreads();

    // Last block to finish: deterministic fixed-order reduction of g_aloss.
    if (s_last) {
        float s = 0.0f;
        for (int i = tid; i < AA; i += 256) s += g_aloss[i];
        s_red[tid] = s;
        __syncthreads();
        for (int o = 128; o; o >>= 1) {
            if (tid < o) s_red[tid] += s_red[tid + o];
            __syncthreads();
        }
        if (tid == 0) {
            out[0] = s_red[0];
            g_done = 0;                      // reset for next graph replay
        }
    }
}

extern "C" void kernel_launch(void* const* d_in, const int* in_sizes, int n_in,
                              void* d_out, int out_size) {
    const float* x       = (const float*)d_in[0];
    const int*   y       = (const int*)  d_in[1];
    const int*   anchors = (const int*)  d_in[2];
    const int*   sampled = (const int*)  d_in[3];
    float*       out     = (float*)d_out;

    (void)in_sizes; (void)n_in; (void)out_size;

    // 4 rows per warp -> 32 rows per 256-thread block
    norm_convert_kernel<<<(NN + 31) / 32, 256>>>(x);
    loss_kernel<<<AA, 256>>>(y, anchors, sampled, out);
}

// round 9
// speedup vs baseline: 1.0388x; 1.0388x over previous
#include <cuda_runtime.h>
#include <cuda_fp16.h>
#include <math.h>

#define NN 100000
#define DD 128
#define AA 4096
#define SS 512
// exp(sim/TEMP) = exp2(sim * 10 * log2(e)) = exp2(sim * 14.4269504089f)

// Scratch (no device mallocs allowed)
__device__ __half g_xh[(size_t)NN * DD];   // normalized fp16 features, 25.6 MB
__device__ float  g_aloss[AA];
__device__ int    g_done = 0;              // ticket counter for last-block reduce

__device__ __forceinline__ float ex2_approx(float v) {
    float r;
    asm("ex2.approx.ftz.f32 %0, %1;" : "=f"(r) : "f"(v));
    return r;
}

// ---------------------------------------------------------------------------
// Kernel 1: fused normalize + fp16 convert. FOUR rows per warp (MLP=4).
// __ldcs: x read exactly once -> evict-first, keep L2 warm for g_xh.
// ---------------------------------------------------------------------------
__global__ void norm_convert_kernel(const float* __restrict__ x) {
    int warp = (blockIdx.x * blockDim.x + threadIdx.x) >> 5;
    int lane = threadIdx.x & 31;
    int r0 = warp * 4;
    if (r0 >= NN) return;

    float4 v[4];
    bool has[4];
#pragma unroll
    for (int k = 0; k < 4; k++) {
        int r = r0 + k;
        has[k] = (r < NN);
        v[k] = has[k]
            ? __ldcs(reinterpret_cast<const float4*>(x + (size_t)r * DD) + lane)
            : make_float4(0.f, 0.f, 0.f, 0.f);
    }

    float s[4];
#pragma unroll
    for (int k = 0; k < 4; k++)
        s[k] = v[k].x * v[k].x + v[k].y * v[k].y + v[k].z * v[k].z + v[k].w * v[k].w;

#pragma unroll
    for (int o = 16; o; o >>= 1) {
#pragma unroll
        for (int k = 0; k < 4; k++)
            s[k] += __shfl_xor_sync(0xFFFFFFFFu, s[k], o);
    }

#pragma unroll
    for (int k = 0; k < 4; k++) {
        if (!has[k]) continue;
        float inv = rsqrtf(s[k]);
        __half2 h[2];
        h[0] = __floats2half2_rn(v[k].x * inv, v[k].y * inv);
        h[1] = __floats2half2_rn(v[k].z * inv, v[k].w * inv);
        reinterpret_cast<uint2*>(g_xh + (size_t)(r0 + k) * DD)[lane] =
            *reinterpret_cast<uint2*>(h);
    }
}

// ---------------------------------------------------------------------------
// Kernel 2: one block (8 warps) per anchor. Half-warp per sample:
// each half-lane owns float4 = 16 B = 8 fp16 -> full 256 B row coalesced.
// Issue-slot diet: fp16x2 dot (1 HMUL2 + 3 HFMA2 instead of 8 cvt + 8 FFMA),
// packed (idx,y) int2 -> one LDS.64/iter, ex2.approx with folded scale.
// 3-deep prefetch ring (data + labels) hides L2 latency.
// ---------------------------------------------------------------------------
__global__ __launch_bounds__(256) void loss_kernel(
    const int* __restrict__ y,
    const int* __restrict__ anchors,
    const int* __restrict__ sampled,
    float* __restrict__ out)
{
    __shared__ int2  s_iy[SS];               // (sample index, sample label)
    __shared__ float s_num[16], s_den[16], s_cnt[16];
    __shared__ int   s_last;
    __shared__ float s_red[256];

    int a    = blockIdx.x;
    int tid  = threadIdx.x;
    int lane = tid & 31;
    int warp = tid >> 5;     // 0..7
    int hw   = lane >> 4;    // half-warp id (0/1)
    int hl   = lane & 15;    // lane within half-warp

    // Stage sample indices + labels packed as int2 (random 4B gathers batched
    // here with 256 threads of MLP, out of the hot loop).
    for (int i = tid; i < SS; i += 256) {
        int si = sampled[(size_t)a * SS + i];
        s_iy[i] = make_int2(si, y[si]);
    }

    int ai = anchors[a];
    int ay = y[ai];

    // Anchor row: 8 fp16 per half-lane, kept as half2 (no conversion)
    __half2 ah[4];
    {
        float4 ar = reinterpret_cast<const float4*>(g_xh + (size_t)ai * DD)[hl];
        const __half2* p = reinterpret_cast<const __half2*>(&ar);
#pragma unroll
        for (int j = 0; j < 4; j++) ah[j] = p[j];
    }
    __syncthreads();

    const int off = warp * 2 + hw;           // this half-warp's sample slot
    float num = 0.0f, den = 0.0f, cnt = 0.0f;

    // 3-deep prefetch ring: sample fragment (16 B) + its label
    float4 buf[3];
    int    ybuf[3];
#pragma unroll
    for (int p = 0; p < 3; p++) {
        int2 iy = s_iy[p * 16 + off];
        buf[p]  = reinterpret_cast<const float4*>(g_xh + (size_t)iy.x * DD)[hl];
        ybuf[p] = iy.y;
    }

#pragma unroll
    for (int i = 0; i < 32; i++) {           // 32 samples per half-warp
        float4 cur = buf[i % 3];
        int    ycur = ybuf[i % 3];
        if (i + 3 < 32) {
            int2 iy = s_iy[(i + 3) * 16 + off];
            buf[i % 3]  = reinterpret_cast<const float4*>(g_xh + (size_t)iy.x * DD)[hl];
            ybuf[i % 3] = iy.y;
        }
        const __half2* sh = reinterpret_cast<const __half2*>(&cur);
        __half2 acc = __hmul2(ah[0], sh[0]);
        acc = __hfma2(ah[1], sh[1], acc);
        acc = __hfma2(ah[2], sh[2], acc);
        acc = __hfma2(ah[3], sh[3], acc);
        float d = __low2float(acc) + __high2float(acc);
        // 16-lane fp32 reduce (xor offsets < 16 stay within the half-warp)
#pragma unroll
        for (int o = 8; o; o >>= 1) d += __shfl_xor_sync(0xFFFFFFFFu, d, o);
        float e = ex2_approx(d * 14.4269504089f);   // exp(d * 10)
        den += e;
        if (ycur == ay) { num += e; cnt += 1.0f; }
    }

    if (hl == 0) { s_num[off] = num; s_den[off] = den; s_cnt[off] = cnt; }
    __syncthreads();

    if (tid == 0) {
        float nm = 0.0f, dn = 0.0f, c = 0.0f;
#pragma unroll
        for (int k = 0; k < 16; k++) { nm += s_num[k]; dn += s_den[k]; c += s_cnt[k]; }
        float loss = 0.0f;
        if (c > 0.0f) loss = (logf(dn) - logf(nm)) / c;  // -log(num/den)/cnt
        g_aloss[a] = loss;
        __threadfence();
        int t = atomicAdd(&g_done, 1);
        s_last = (t == AA - 1) ? 1 : 0;
    }
    __syncthreads();

    // Last block to finish: deterministic fixed-order reduction of g_aloss.
    if (s_last) {
        float s = 0.0f;
        for (int i = tid; i < AA; i += 256) s += g_aloss[i];
        s_red[tid] = s;
        __syncthreads();
        for (int o = 128; o; o >>= 1) {
            if (tid < o) s_red[tid] += s_red[tid + o];
            __syncthreads();
        }
        if (tid == 0) {
            out[0] = s_red[0];
            g_done = 0;                      // reset for next graph replay
        }
    }
}

extern "C" void kernel_launch(void* const* d_in, const int* in_sizes, int n_in,
                              void* d_out, int out_size) {
    const float* x       = (const float*)d_in[0];
    const int*   y       = (const int*)  d_in[1];
    const int*   anchors = (const int*)  d_in[2];
    const int*   sampled = (const int*)  d_in[3];
    float*       out     = (float*)d_out;

    (void)in_sizes; (void)n_in; (void)out_size;

    // 4 rows per warp -> 32 rows per 256-thread block
    norm_convert_kernel<<<(NN + 31) / 32, 256>>>(x);
    loss_kernel<<<AA, 256>>>(y, anchors, sampled, out);
}